// round 11
// baseline (speedup 1.0000x reference)
#include <cuda_runtime.h>
#include <stdint.h>
#include <math.h>

#define NND 2048
#define NE  65536
#define H1  32
#define H2  20
#define NNSQ (NND*NND)

// -------- scratch (device globals; no runtime allocation) --------
__device__ __align__(16) float d_deg[NND];      // 1 + in-degree
__device__ __align__(16) float d_h1[NND*H1];
__device__ __align__(16) float d_h2[NND*H2];
__device__ int   d_rowoff[NND];                  // CSR row offsets (by dst)
__device__ int   d_cursor[NND];                  // scatter cursors
__device__ int   d_srcs[NE];                     // edge sources sorted by dst
__device__ float d_xcum[H2];                     // column sums of o2
__device__ float    d_rowval[NND];
__device__ unsigned d_rowidx[NND];
__device__ float    d_rowm[NND];
__device__ float    d_rowz[NND];
__device__ int      d_ei64;   // 1 if edge_index is int64, 0 if int32

// dual-dtype edge index accessor (pos in [0, 2*NE))
__device__ __forceinline__ int load_ei(const void* ei, int pos, int is64) {
    if (is64) return (int)((const long long*)ei)[pos];
    return ((const int*)ei)[pos];
}

// pair combine: max value, tie -> smaller index (first occurrence)
__device__ __forceinline__ void pair_take(float& v, unsigned& i, float v2, unsigned i2) {
    if (v2 > v || (v2 == v && i2 < i)) { v = v2; i = i2; }
}

__device__ __forceinline__ void warp_pair_reduce(float& v, unsigned& i) {
    #pragma unroll
    for (int o = 16; o; o >>= 1) {
        float    v2 = __shfl_xor_sync(0xffffffffu, v, o);
        unsigned i2 = __shfl_xor_sync(0xffffffffu, i, o);
        pair_take(v, i, v2, i2);
    }
}

__device__ __forceinline__ void block_pair_reduce(float& v, unsigned& i,
                                                  float* sval, unsigned* sidx) {
    warp_pair_reduce(v, i);
    int lane = threadIdx.x & 31, wid = threadIdx.x >> 5;
    if (lane == 0) { sval[wid] = v; sidx[wid] = i; }
    __syncthreads();
    if (wid == 0) {
        int nw = (blockDim.x + 31) >> 5;
        if (lane < nw) { v = sval[lane]; i = sidx[lane]; }
        else           { v = -3.402823e38f; i = 0xFFFFFFFFu; }
        warp_pair_reduce(v, i);
        if (lane == 0) { sval[0] = v; sidx[0] = i; }
    }
    __syncthreads();
    v = sval[0]; i = sidx[0];
    __syncthreads();
}

__device__ __forceinline__ float block_reduce_max(float v, float* red) {
    __syncthreads();
    int lane = threadIdx.x & 31, wid = threadIdx.x >> 5;
    #pragma unroll
    for (int o = 16; o; o >>= 1) v = fmaxf(v, __shfl_xor_sync(0xffffffffu, v, o));
    if (lane == 0) red[wid] = v;
    __syncthreads();
    if (wid == 0) {
        int nw = (blockDim.x + 31) >> 5;
        v = (lane < nw) ? red[lane] : -3.402823e38f;
        #pragma unroll
        for (int o = 16; o; o >>= 1) v = fmaxf(v, __shfl_xor_sync(0xffffffffu, v, o));
        if (lane == 0) red[0] = v;
    }
    __syncthreads();
    return red[0];
}

__device__ __forceinline__ float block_reduce_sum(float v, float* red) {
    __syncthreads();
    int lane = threadIdx.x & 31, wid = threadIdx.x >> 5;
    #pragma unroll
    for (int o = 16; o; o >>= 1) v += __shfl_xor_sync(0xffffffffu, v, o);
    if (lane == 0) red[wid] = v;
    __syncthreads();
    if (wid == 0) {
        int nw = (blockDim.x + 31) >> 5;
        v = (lane < nw) ? red[lane] : 0.f;
        #pragma unroll
        for (int o = 16; o; o >>= 1) v += __shfl_xor_sync(0xffffffffu, v, o);
        if (lane == 0) red[0] = v;
    }
    __syncthreads();
    return red[0];
}

// -------- kernels --------
// init scratch + detect edge dtype (int64 values must all be in [0, NND))
__global__ void k_init(const void* __restrict__ ei) {
    int i = blockIdx.x * blockDim.x + threadIdx.x;
    if (i < NND*H1) d_h1[i] = 0.f;
    if (i < NND)    d_deg[i] = 1.f;   // self loop
    if (i < H2)     d_xcum[i] = 0.f;
    if (i == 0) {
        const long long* p = (const long long*)ei;
        int is64 = 1;
        for (int k = 0; k < 16; k++) {
            long long v = p[k];
            if (v < 0 || v >= NND) { is64 = 0; break; }
        }
        d_ei64 = is64;
    }
}

// h1 = x @ W1 (2048x2048 @ 2048x32); 32-way k-split, atomic accumulate.
// blockIdx.y==0 slice also performs the degree atomics.
__global__ void __launch_bounds__(256) k_gemm1(const float* __restrict__ X,
                                               const float* __restrict__ W,
                                               const void* __restrict__ ei) {
    __shared__ float Xs[64][64];
    __shared__ float Ws[64][H1];
    int t = threadIdx.x;
    if (blockIdx.y == 0) {
        int is64 = d_ei64;
        for (int e = blockIdx.x * 256 + t; e < NE; e += 32 * 256) {
            int d = load_ei(ei, NE + e, is64);
            if ((unsigned)d < NND) atomicAdd(&d_deg[d], 1.f);
        }
    }
    int row0 = blockIdx.x * 64;
    int k0 = blockIdx.y * 64;
    int tx = t & 31;
    int ty = t >> 5;
    float acc[8] = {0,0,0,0,0,0,0,0};
    #pragma unroll
    for (int i = 0; i < 4; i++) {
        int idx = t + i * 256;
        int r = idx >> 4, c = idx & 15;
        float4 v = __ldg((const float4*)&X[(size_t)(row0 + r)*NND + k0 + c*4]);
        Xs[r][4*c + 0] = v.x; Xs[r][4*c + 1] = v.y;
        Xs[r][4*c + 2] = v.z; Xs[r][4*c + 3] = v.w;
    }
    #pragma unroll
    for (int i = 0; i < 2; i++) {
        int idx = t + i * 256;
        int r = idx >> 3, c = idx & 7;
        float4 v = __ldg((const float4*)&W[(size_t)(k0 + r)*H1 + 4*c]);
        Ws[r][4*c + 0] = v.x; Ws[r][4*c + 1] = v.y;
        Ws[r][4*c + 2] = v.z; Ws[r][4*c + 3] = v.w;
    }
    __syncthreads();
    #pragma unroll 8
    for (int kk = 0; kk < 64; kk++) {
        float wv = Ws[kk][tx];
        #pragma unroll
        for (int r = 0; r < 8; r++) acc[r] = fmaf(Xs[ty + r*8][kk], wv, acc[r]);
    }
    #pragma unroll
    for (int r = 0; r < 8; r++)
        atomicAdd(&d_h1[(size_t)(row0 + ty + r*8)*H1 + tx], acc[r]);
}

// exclusive scan of in-degree (deg-1) over 2048 nodes -> rowoff, cursor
__global__ void __launch_bounds__(1024) k_scan() {
    __shared__ int warpsum[32];
    int t = threadIdx.x;            // 0..1023, each handles elements 2t, 2t+1
    int c0 = (int)(d_deg[2*t]     - 0.5f);
    int c1 = (int)(d_deg[2*t + 1] - 0.5f);
    int p = c0 + c1;
    int lane = t & 31, wid = t >> 5;
    int v = p;
    #pragma unroll
    for (int o = 1; o < 32; o <<= 1) {
        int u = __shfl_up_sync(0xffffffffu, v, o);
        if (lane >= o) v += u;
    }
    if (lane == 31) warpsum[wid] = v;
    __syncthreads();
    if (wid == 0) {
        int w = warpsum[lane];
        #pragma unroll
        for (int o = 1; o < 32; o <<= 1) {
            int u = __shfl_up_sync(0xffffffffu, w, o);
            if (lane >= o) w += u;
        }
        warpsum[lane] = w;
    }
    __syncthreads();
    int base = (wid > 0) ? warpsum[wid - 1] : 0;
    int excl = base + v - p;        // exclusive prefix for element 2t
    d_rowoff[2*t]     = excl;
    d_rowoff[2*t + 1] = excl + c0;
    d_cursor[2*t]     = excl;
    d_cursor[2*t + 1] = excl + c0;
}

// scatter edge sources into CSR order by destination
__global__ void __launch_bounds__(256) k_scatter(const void* __restrict__ ei) {
    int e = blockIdx.x * 256 + threadIdx.x;
    if (e >= NE) return;
    int is64 = d_ei64;
    int s = load_ei(ei, e, is64);
    int d = load_ei(ei, NE + e, is64);
    if ((unsigned)s >= NND || (unsigned)d >= NND) return;
    int pos = atomicAdd(&d_cursor[d], 1);
    d_srcs[pos] = s;
}

// layer-1 gather aggregation + relu + gemm2, fused. One warp per node.
__global__ void __launch_bounds__(256) k_agg1g(const float* __restrict__ W2,
                                               const float* __restrict__ b1) {
    __shared__ float W2s[H1][H2];
    int t = threadIdx.x;
    for (int i = t; i < H1*H2; i += 256) W2s[i / H2][i % H2] = W2[i];
    __syncthreads();
    int w = t >> 5, lane = t & 31;
    int n = blockIdx.x * 8 + w;
    float degn = d_deg[n];
    float dinvd = rsqrtf(degn);
    int start = d_rowoff[n];
    int end = start + (int)(degn - 0.5f);
    float acc = 0.f;
    int i = start;
    for (; i + 4 <= end; i += 4) {
        int s0 = d_srcs[i], s1 = d_srcs[i+1], s2 = d_srcs[i+2], s3 = d_srcs[i+3];
        float n0 = rsqrtf(d_deg[s0]), n1 = rsqrtf(d_deg[s1]);
        float n2 = rsqrtf(d_deg[s2]), n3 = rsqrtf(d_deg[s3]);
        float v0 = d_h1[s0*H1 + lane], v1 = d_h1[s1*H1 + lane];
        float v2 = d_h1[s2*H1 + lane], v3 = d_h1[s3*H1 + lane];
        acc = fmaf(v0, n0, acc); acc = fmaf(v1, n1, acc);
        acc = fmaf(v2, n2, acc); acc = fmaf(v3, n3, acc);
    }
    for (; i < end; i++) {
        int s0 = d_srcs[i];
        acc = fmaf(d_h1[s0*H1 + lane], rsqrtf(d_deg[s0]), acc);
    }
    float self = d_h1[n*H1 + lane] * dinvd * dinvd;
    float o1 = fmaxf(acc * dinvd + self + __ldg(&b1[lane]), 0.f);
    float s = 0.f;
    #pragma unroll
    for (int k = 0; k < H1; k++) {
        float ok = __shfl_sync(0xffffffffu, o1, k);
        if (lane < H2) s = fmaf(ok, W2s[k][lane], s);
    }
    if (lane < H2) d_h2[n*H2 + lane] = s;
}

// layer-2 gather aggregation + relu + column-mean partials, fused. Warp per node.
__global__ void __launch_bounds__(256) k_agg2g(const float* __restrict__ b2) {
    __shared__ float colsum[8][H2];
    int t = threadIdx.x;
    int w = t >> 5, lane = t & 31;
    int n = blockIdx.x * 8 + w;
    float degn = d_deg[n];
    float dinvd = rsqrtf(degn);
    int start = d_rowoff[n];
    int end = start + (int)(degn - 0.5f);
    float acc = 0.f;
    int i = start;
    for (; i + 4 <= end; i += 4) {
        int s0 = d_srcs[i], s1 = d_srcs[i+1], s2 = d_srcs[i+2], s3 = d_srcs[i+3];
        float n0 = rsqrtf(d_deg[s0]), n1 = rsqrtf(d_deg[s1]);
        float n2 = rsqrtf(d_deg[s2]), n3 = rsqrtf(d_deg[s3]);
        if (lane < H2) {
            float v0 = d_h2[s0*H2 + lane], v1 = d_h2[s1*H2 + lane];
            float v2 = d_h2[s2*H2 + lane], v3 = d_h2[s3*H2 + lane];
            acc = fmaf(v0, n0, acc); acc = fmaf(v1, n1, acc);
            acc = fmaf(v2, n2, acc); acc = fmaf(v3, n3, acc);
        }
    }
    for (; i < end; i++) {
        int s0 = d_srcs[i];
        float n0 = rsqrtf(d_deg[s0]);
        if (lane < H2) acc = fmaf(d_h2[s0*H2 + lane], n0, acc);
    }
    float o2 = 0.f;
    if (lane < H2) {
        float self = d_h2[n*H2 + lane] * dinvd * dinvd;
        o2 = fmaxf(acc * dinvd + self + __ldg(&b2[lane]), 0.f);
        colsum[w][lane] = o2;
    }
    __syncthreads();
    if (w == 0 && lane < H2) {
        float s = 0.f;
        #pragma unroll
        for (int r = 0; r < 8; r++) s += colsum[r][lane];
        atomicAdd(&d_xcum[lane], s);
    }
}

// Fused: logits row -> softmax stats -> per-row argmax (no probs store)
__global__ void __launch_bounds__(512) k_logits(const float* __restrict__ aW,
                                                const float* __restrict__ ab) {
    __shared__ float xa[H2];
    __shared__ float red[32];
    __shared__ float    sval[16];
    __shared__ unsigned sidx[16];
    int t = threadIdx.x;
    int row = blockIdx.x;
    if (t < H2) xa[t] = d_xcum[t] * (1.f / NND);
    __syncthreads();
    size_t base = (size_t)row * NND;
    float l[4];
    {
        float4 a0 = __ldcs((const float4*)&ab[base + 4*t]);
        l[0]=a0.x; l[1]=a0.y; l[2]=a0.z; l[3]=a0.w;
    }
    #pragma unroll
    for (int k = 0; k < H2; k++) {
        float xv = xa[k];
        float4 v0 = __ldcs((const float4*)&aW[(size_t)k * NNSQ + base + 4*t]);
        l[0] = fmaf(xv, v0.x, l[0]); l[1] = fmaf(xv, v0.y, l[1]);
        l[2] = fmaf(xv, v0.z, l[2]); l[3] = fmaf(xv, v0.w, l[3]);
    }
    float m = fmaxf(fmaxf(l[0], l[1]), fmaxf(l[2], l[3]));
    m = block_reduce_max(m, red);
    float e[4]; float s = 0.f;
    #pragma unroll
    for (int c = 0; c < 4; c++) { e[c] = expf(l[c] - m); s += e[c]; }
    s = block_reduce_sum(s, red);
    float p[4];
    #pragma unroll
    for (int c = 0; c < 4; c++) p[c] = e[c] / s;
    float bv = p[0]; unsigned bc = (unsigned)(4*t);
    #pragma unroll
    for (int c = 1; c < 4; c++)
        if (p[c] > bv) { bv = p[c]; bc = (unsigned)(4*t + c); }
    unsigned gi = (unsigned)base + bc;
    warp_pair_reduce(bv, gi);
    int lane = t & 31, wid = t >> 5;
    if (lane == 0) { sval[wid] = bv; sidx[wid] = gi; }
    __syncthreads();
    if (t == 0) {
        float v = sval[0]; unsigned i = sidx[0];
        #pragma unroll
        for (int w = 1; w < 16; w++) pair_take(v, i, sval[w], sidx[w]);
        d_rowval[row] = v; d_rowidx[row] = i;
        d_rowm[row] = m; d_rowz[row] = s;
    }
}

// Single-block tail: global argmax -> prefix argmax (recompute row r1) -> output
__global__ void __launch_bounds__(256) k_tail(const float* __restrict__ aW,
                                              const float* __restrict__ ab,
                                              const float* __restrict__ cW,
                                              const float* __restrict__ cb,
                                              float* __restrict__ out, int out_size) {
    __shared__ float    sval[8];
    __shared__ unsigned sidx[8];
    __shared__ float xa[H2];
    int t = threadIdx.x;
    if (t < H2) xa[t] = d_xcum[t] * (1.f / NND);
    __syncthreads();

    float v = -1.f; unsigned i = 0xFFFFFFFFu;
    for (int r = t; r < NND; r += 256) pair_take(v, i, d_rowval[r], d_rowidx[r]);
    block_pair_reduce(v, i, sval, sidx);
    unsigned idx1 = i;
    unsigned r1 = idx1 >> 11, c1 = idx1 & 2047u;

    float v2 = -1.f; unsigned i2 = 0xFFFFFFFFu;
    for (unsigned r = t; r < r1; r += 256) pair_take(v2, i2, d_rowval[r], d_rowidx[r]);
    if (c1 > 0) {
        float m1 = d_rowm[r1], z1 = d_rowz[r1];
        size_t base = (size_t)r1 * NND;
        for (unsigned c = t; c < c1; c += 256) {
            float l = __ldg(&ab[base + c]);
            #pragma unroll
            for (int k = 0; k < H2; k++)
                l = fmaf(xa[k], __ldg(&aW[(size_t)k * NNSQ + base + c]), l);
            float p = expf(l - m1) / z1;
            pair_take(v2, i2, p, (unsigned)base + c);
        }
    }
    block_pair_reduce(v2, i2, sval, sidx);
    unsigned idx2 = (v2 >= 0.f) ? i2 : 0u;

    if (t == 0) {
        unsigned a0 = idx1 >> 11, a1 = idx1 & 2047u;
        unsigned a2 = idx2 >> 11, a3 = idx2 & 2047u;
        float m0 = d_rowm[0], z0 = d_rowz[0];
        unsigned ai[4] = {a0, a1, a2, a3};
        float lp[4];
        #pragma unroll
        for (int q = 0; q < 4; q++) {
            unsigned j = ai[q];
            float l = ab[j];
            #pragma unroll
            for (int k = 0; k < H2; k++)
                l = fmaf(xa[k], aW[(size_t)k * NNSQ + j], l);
            float p = expf(l - m0) / z0;
            lp[q] = -logf(p);
        }
        float critic = cb[0];
        #pragma unroll
        for (int k = 0; k < H2; k++) critic = fmaf(xa[k], cW[k], critic);
        float o[9];
        o[0] = (float)a0; o[1] = (float)a1; o[2] = (float)a2; o[3] = (float)a3;
        o[4] = lp[0]; o[5] = lp[1]; o[6] = lp[2]; o[7] = lp[3];
        o[8] = critic;
        int n = out_size < 9 ? out_size : 9;
        for (int q = 0; q < n; q++) out[q] = o[q];
    }
}

extern "C" void kernel_launch(void* const* d_in, const int* in_sizes, int n_in,
                              void* d_out, int out_size) {
    const float* x   = (const float*)d_in[0];
    const void*  ei  = d_in[1];
    const float* W1  = (const float*)d_in[2];
    const float* b1  = (const float*)d_in[3];
    const float* W2  = (const float*)d_in[4];
    const float* b2  = (const float*)d_in[5];
    const float* aW  = (const float*)d_in[6];
    const float* ab  = (const float*)d_in[7];
    const float* cW  = (const float*)d_in[8];
    const float* cb  = (const float*)d_in[9];
    float* out = (float*)d_out;

    k_init   <<<256, 256>>>(ei);
    k_gemm1  <<<dim3(32, 32), 256>>>(x, W1, ei);
    k_scan   <<<1,   1024>>>();
    k_scatter<<<256, 256>>>(ei);
    k_agg1g  <<<256, 256>>>(W2, b1);
    k_agg2g  <<<256, 256>>>(b2);
    k_logits <<<2048,512>>>(aW, ab);
    k_tail   <<<1,   256>>>(aW, ab, cW, cb, out, out_size);
}